// round 1
// baseline (speedup 1.0000x reference)
#include <cuda_runtime.h>
#include <cuda_bf16.h>
#include <math.h>

// Problem constants
#define BB 4
#define NSEQ 4096        // H*W = 64*64
#define CC 256
#define DD 32

// Scratch (device globals; no runtime allocation allowed)
__device__ float g_q[BB * NSEQ * DD];
__device__ float g_k[BB * NSEQ * DD];
__device__ float g_v[BB * NSEQ * CC];
__device__ float g_att[BB * NSEQ * CC];

// ---------------------------------------------------------------------------
// Generic tiled GEMM: C[M,N] = A[M,K] @ W[K,N] + bias[N] (+ res[M,N])
// BM=64, BN=64, BK=16, 256 threads, 4x4 register tile.
// M % 64 == 0 and K % 16 == 0 are assumed (true for all our shapes).
// ---------------------------------------------------------------------------
__global__ __launch_bounds__(256) void gemm_bias_kernel(
    const float* __restrict__ A, const float* __restrict__ W,
    const float* __restrict__ bias, const float* __restrict__ res,
    float* __restrict__ Cm, int M, int N, int K)
{
    __shared__ float As[16][65];   // [k][m], padded
    __shared__ float Ws[16][64];   // [k][n]

    const int m0 = blockIdx.y * 64;
    const int n0 = blockIdx.x * 64;
    const int tid = threadIdx.x;
    const int tm = tid >> 4;       // 0..15
    const int tn = tid & 15;       // 0..15

    float acc[4][4];
#pragma unroll
    for (int i = 0; i < 4; i++)
#pragma unroll
        for (int j = 0; j < 4; j++) acc[i][j] = 0.f;

    for (int k0 = 0; k0 < K; k0 += 16) {
        // Load A tile (64x16) transposed into As
#pragma unroll
        for (int i = 0; i < 4; i++) {
            int l = tid + i * 256;          // 0..1023
            int ar = l >> 4, ac = l & 15;
            As[ac][ar] = A[(size_t)(m0 + ar) * K + k0 + ac];
        }
        // Load W tile (16x64)
#pragma unroll
        for (int i = 0; i < 4; i++) {
            int l = tid + i * 256;
            int wr = l >> 6, wc = l & 63;
            int col = n0 + wc;
            Ws[wr][wc] = (col < N) ? W[(size_t)(k0 + wr) * N + col] : 0.f;
        }
        __syncthreads();

#pragma unroll
        for (int kk = 0; kk < 16; kk++) {
            float a[4], b[4];
#pragma unroll
            for (int i = 0; i < 4; i++) a[i] = As[kk][tm * 4 + i];
#pragma unroll
            for (int j = 0; j < 4; j++) b[j] = Ws[kk][tn * 4 + j];
#pragma unroll
            for (int i = 0; i < 4; i++)
#pragma unroll
                for (int j = 0; j < 4; j++)
                    acc[i][j] += a[i] * b[j];
        }
        __syncthreads();
    }

#pragma unroll
    for (int i = 0; i < 4; i++) {
        int row = m0 + tm * 4 + i;
#pragma unroll
        for (int j = 0; j < 4; j++) {
            int col = n0 + tn * 4 + j;
            if (col < N) {
                float v = acc[i][j] + bias[col];
                if (res) v += res[(size_t)row * N + col];
                Cm[(size_t)row * N + col] = v;
            }
        }
    }
}

// ---------------------------------------------------------------------------
// Flash attention, fp32. BM=BN=64, D=32, DV=256. 256 threads.
// smem: Qs[64*33] Ks[64*33] Vs[64*260] Ss[64*65] m/l/alpha[64 each]
// ---------------------------------------------------------------------------
#define QSTR 33
#define KSTR 33
#define VSTR 260
#define SSTR 65
#define FLASH_SMEM_FLOATS (64*QSTR + 64*KSTR + 64*VSTR + 64*SSTR + 192)

__global__ __launch_bounds__(256, 2) void flash_kernel(
    const float* __restrict__ Q, const float* __restrict__ Kp,
    const float* __restrict__ V, float* __restrict__ O)
{
    extern __shared__ float sm[];
    float* Qs   = sm;
    float* Ks   = Qs + 64 * QSTR;
    float* Vs   = Ks + 64 * KSTR;
    float* Ss   = Vs + 64 * VSTR;
    float* mrow = Ss + 64 * SSTR;
    float* lrow = mrow + 64;
    float* arow = lrow + 64;

    const int tid = threadIdx.x;
    const int qb = blockIdx.x;
    const int b  = blockIdx.y;

    const float* Qb = Q + ((size_t)b * NSEQ + qb * 64) * DD;
    const float* Kb = Kp + (size_t)b * NSEQ * DD;
    const float* Vb = V + (size_t)b * NSEQ * CC;

    // Load Q tile, pre-scaled by 1/sqrt(D)
    const float scale = 0.17677669529663687f;
#pragma unroll
    for (int i = 0; i < 8; i++) {
        int l = tid + i * 256;     // 0..2047
        int r = l >> 5, d = l & 31;
        Qs[r * QSTR + d] = Qb[(size_t)r * DD + d] * scale;
    }
    if (tid < 64) { mrow[tid] = -INFINITY; lrow[tid] = 0.f; }

    // PV mapping: lanes within a warp cover 16 row-groups x 2 col-groups
    // -> Vs reads are 2-address broadcasts (conflict-free).
    const int cg = tid >> 4;       // 0..15 -> cols cg*16..+15
    const int rg = tid & 15;       // 0..15 -> rows rg*4..+3
    const int r0 = rg * 4;
    const int c0 = cg * 16;

    // Score mapping: thread computes row rS, 16 cols starting jg*16
    const int rS = tid >> 2;       // 0..63
    const int jg = tid & 3;        // 0..3

    float acc[4][16];
#pragma unroll
    for (int i = 0; i < 4; i++)
#pragma unroll
        for (int j = 0; j < 16; j++) acc[i][j] = 0.f;

    for (int kt = 0; kt < NSEQ / 64; kt++) {
        // Load K tile (64x32)
#pragma unroll
        for (int i = 0; i < 8; i++) {
            int l = tid + i * 256;
            int r = l >> 5, d = l & 31;
            Ks[r * KSTR + d] = Kb[((size_t)kt * 64 + r) * DD + d];
        }
        // Load V tile (64x256) via float4
        const float4* Vg = (const float4*)(Vb + (size_t)kt * 64 * CC);
#pragma unroll
        for (int i = 0; i < 16; i++) {
            int l = tid + i * 256;          // 0..4095 float4s
            int r = l >> 6, c4 = l & 63;
            *(float4*)&Vs[r * VSTR + c4 * 4] = Vg[r * 64 + c4];
        }
        __syncthreads();

        // S = Q @ K^T (scaled already): 16 scores per thread
#pragma unroll 4
        for (int jj = 0; jj < 16; jj++) {
            int j = jg * 16 + jj;
            float s = 0.f;
#pragma unroll
            for (int d = 0; d < 32; d++)
                s += Qs[rS * QSTR + d] * Ks[j * KSTR + d];
            Ss[rS * SSTR + j] = s;
        }
        __syncthreads();

        // Online softmax row update (one thread per row)
        if (tid < 64) {
            int r = tid;
            float mo = mrow[r];
            float mx = mo;
#pragma unroll 8
            for (int j = 0; j < 64; j++) mx = fmaxf(mx, Ss[r * SSTR + j]);
            float al = __expf(mo - mx);
            float lsum = lrow[r] * al;
#pragma unroll 4
            for (int j = 0; j < 64; j++) {
                float p = __expf(Ss[r * SSTR + j] - mx);
                Ss[r * SSTR + j] = p;
                lsum += p;
            }
            mrow[r] = mx; lrow[r] = lsum; arow[r] = al;
        }
        __syncthreads();

        // Rescale accumulators, then acc += P @ V
        float al[4];
#pragma unroll
        for (int rr = 0; rr < 4; rr++) al[rr] = arow[r0 + rr];
#pragma unroll
        for (int rr = 0; rr < 4; rr++)
#pragma unroll
            for (int cc2 = 0; cc2 < 16; cc2++) acc[rr][cc2] *= al[rr];

        for (int j = 0; j < 64; j++) {
            float p[4];
#pragma unroll
            for (int rr = 0; rr < 4; rr++) p[rr] = Ss[(r0 + rr) * SSTR + j];
#pragma unroll
            for (int i4 = 0; i4 < 4; i4++) {
                float4 vv = *(const float4*)&Vs[j * VSTR + c0 + i4 * 4];
#pragma unroll
                for (int rr = 0; rr < 4; rr++) {
                    acc[rr][i4 * 4 + 0] += p[rr] * vv.x;
                    acc[rr][i4 * 4 + 1] += p[rr] * vv.y;
                    acc[rr][i4 * 4 + 2] += p[rr] * vv.z;
                    acc[rr][i4 * 4 + 3] += p[rr] * vv.w;
                }
            }
        }
        __syncthreads();   // protect Ks/Vs/Ss before next tile
    }

    // Epilogue: divide by row sums, store attended
    float* Ob = O + ((size_t)b * NSEQ + qb * 64) * CC;
#pragma unroll
    for (int rr = 0; rr < 4; rr++) {
        float inv = 1.f / lrow[r0 + rr];
#pragma unroll
        for (int i4 = 0; i4 < 4; i4++) {
            float4 o;
            o.x = acc[rr][i4 * 4 + 0] * inv;
            o.y = acc[rr][i4 * 4 + 1] * inv;
            o.z = acc[rr][i4 * 4 + 2] * inv;
            o.w = acc[rr][i4 * 4 + 3] * inv;
            *(float4*)&Ob[(size_t)(r0 + rr) * CC + c0 + i4 * 4] = o;
        }
    }
}

// ---------------------------------------------------------------------------
extern "C" void kernel_launch(void* const* d_in, const int* in_sizes, int n_in,
                              void* d_out, int out_size)
{
    const float* x  = (const float*)d_in[0];
    const float* wq = (const float*)d_in[1];
    const float* bq = (const float*)d_in[2];
    const float* wk = (const float*)d_in[3];
    const float* bk = (const float*)d_in[4];
    const float* wv = (const float*)d_in[5];
    const float* bv = (const float*)d_in[6];
    const float* wo = (const float*)d_in[7];
    const float* bo = (const float*)d_in[8];
    float* out = (float*)d_out;

    float *qp, *kp, *vp, *ap;
    cudaGetSymbolAddress((void**)&qp, g_q);
    cudaGetSymbolAddress((void**)&kp, g_k);
    cudaGetSymbolAddress((void**)&vp, g_v);
    cudaGetSymbolAddress((void**)&ap, g_att);

    const int M = BB * NSEQ;   // 16384

    // Projections
    gemm_bias_kernel<<<dim3(1, M / 64), 256>>>(x, wq, bq, nullptr, qp, M, DD, CC);
    gemm_bias_kernel<<<dim3(1, M / 64), 256>>>(x, wk, bk, nullptr, kp, M, DD, CC);
    gemm_bias_kernel<<<dim3(CC / 64, M / 64), 256>>>(x, wv, bv, nullptr, vp, M, CC, CC);

    // Flash attention
    size_t smem = FLASH_SMEM_FLOATS * sizeof(float);
    cudaFuncSetAttribute(flash_kernel, cudaFuncAttributeMaxDynamicSharedMemorySize, (int)smem);
    flash_kernel<<<dim3(NSEQ / 64, BB), 256, smem>>>(qp, kp, vp, ap);

    // Output projection + bias + residual -> d_out
    gemm_bias_kernel<<<dim3(CC / 64, M / 64), 256>>>(ap, wo, bo, x, out, M, CC, CC);
}

// round 2
// speedup vs baseline: 2.8775x; 2.8775x over previous
#include <cuda_runtime.h>
#include <cuda_bf16.h>
#include <math.h>
#include <stdint.h>

// Problem constants
#define BB 4
#define NSEQ 4096        // H*W = 64*64
#define CC 256
#define DD 32

// Scratch (device globals; no runtime allocation allowed)
__device__ float g_q[BB * NSEQ * DD];
__device__ float g_k[BB * NSEQ * DD];
__device__ float g_v[BB * NSEQ * CC];
__device__ float g_att[BB * NSEQ * CC];

// ---------------------------------------------------------------------------
// Generic tiled GEMM: C[M,N] = A[M,K] @ W[K,N] + bias[N] (+ res[M,N])
// BM=64, BN=64, BK=16, 256 threads, 4x4 register tile.
// ---------------------------------------------------------------------------
__global__ __launch_bounds__(256) void gemm_bias_kernel(
    const float* __restrict__ A, const float* __restrict__ W,
    const float* __restrict__ bias, const float* __restrict__ res,
    float* __restrict__ Cm, int M, int N, int K)
{
    __shared__ float As[16][65];   // [k][m], padded
    __shared__ float Ws[16][64];   // [k][n]

    const int m0 = blockIdx.y * 64;
    const int n0 = blockIdx.x * 64;
    const int tid = threadIdx.x;
    const int tm = tid >> 4;       // 0..15
    const int tn = tid & 15;       // 0..15

    float acc[4][4];
#pragma unroll
    for (int i = 0; i < 4; i++)
#pragma unroll
        for (int j = 0; j < 4; j++) acc[i][j] = 0.f;

    for (int k0 = 0; k0 < K; k0 += 16) {
#pragma unroll
        for (int i = 0; i < 4; i++) {
            int l = tid + i * 256;
            int ar = l >> 4, ac = l & 15;
            As[ac][ar] = A[(size_t)(m0 + ar) * K + k0 + ac];
        }
#pragma unroll
        for (int i = 0; i < 4; i++) {
            int l = tid + i * 256;
            int wr = l >> 6, wc = l & 63;
            int col = n0 + wc;
            Ws[wr][wc] = (col < N) ? W[(size_t)(k0 + wr) * N + col] : 0.f;
        }
        __syncthreads();

#pragma unroll
        for (int kk = 0; kk < 16; kk++) {
            float a[4], b[4];
#pragma unroll
            for (int i = 0; i < 4; i++) a[i] = As[kk][tm * 4 + i];
#pragma unroll
            for (int j = 0; j < 4; j++) b[j] = Ws[kk][tn * 4 + j];
#pragma unroll
            for (int i = 0; i < 4; i++)
#pragma unroll
                for (int j = 0; j < 4; j++)
                    acc[i][j] += a[i] * b[j];
        }
        __syncthreads();
    }

#pragma unroll
    for (int i = 0; i < 4; i++) {
        int row = m0 + tm * 4 + i;
#pragma unroll
        for (int j = 0; j < 4; j++) {
            int col = n0 + tn * 4 + j;
            if (col < N) {
                float v = acc[i][j] + bias[col];
                if (res) v += res[(size_t)row * N + col];
                Cm[(size_t)row * N + col] = v;
            }
        }
    }
}

// ---------------------------------------------------------------------------
// TF32 tensor-core flash attention.
// 256 threads (8 warps). BM=BN=64, D=32, DV=256.
// S-phase : warp w computes S rows [16*(w&3), +16) x cols [32*(w>>2), +32)
// PV-phase: warp w computes O rows [32*(w&1), +32) x cols [64*(w>>1), +64)
// smem: Ks[64][36] | Vs[64][264] | Ps[64][68] | m/l/alpha[64 each]
// ---------------------------------------------------------------------------
#define KSTR 36
#define VSTR 264
#define PSTR 68
#define KS_OFF 0
#define VS_OFF (64 * KSTR)                 // 2304
#define PS_OFF (VS_OFF + 64 * VSTR)       // 19200
#define ROW_OFF (PS_OFF + 64 * PSTR)      // 23552
#define FLASH_SMEM_FLOATS (ROW_OFF + 192) // 23744

__device__ __forceinline__ uint32_t f2tf(float f) {
    uint32_t u;
    asm("cvt.rna.tf32.f32 %0, %1;" : "=r"(u) : "f"(f));
    return u;
}

__device__ __forceinline__ void mma_tf32(float* c, const uint32_t* a, const uint32_t* b) {
    asm volatile(
        "mma.sync.aligned.m16n8k8.row.col.f32.tf32.tf32.f32 "
        "{%0,%1,%2,%3}, {%4,%5,%6,%7}, {%8,%9}, {%0,%1,%2,%3};\n"
        : "+f"(c[0]), "+f"(c[1]), "+f"(c[2]), "+f"(c[3])
        : "r"(a[0]), "r"(a[1]), "r"(a[2]), "r"(a[3]), "r"(b[0]), "r"(b[1]));
}

__global__ __launch_bounds__(256, 2) void flash_tc_kernel(
    const float* __restrict__ Q, const float* __restrict__ Kg,
    const float* __restrict__ V, float* __restrict__ O)
{
    extern __shared__ float sm[];
    float* Ks   = sm + KS_OFF;
    float* Vs   = sm + VS_OFF;
    float* Ps   = sm + PS_OFF;
    float* mrow = sm + ROW_OFF;
    float* lrow = mrow + 64;
    float* arow = lrow + 64;

    const int tid  = threadIdx.x;
    const int lane = tid & 31;
    const int w    = tid >> 5;
    const int g    = lane >> 2;   // group id 0..7
    const int t    = lane & 3;    // thread-in-group 0..3

    const int qb = blockIdx.x;
    const int b  = blockIdx.y;

    const float* Qb = Q  + ((size_t)b * NSEQ + qb * 64) * DD;
    const float* Kb = Kg + (size_t)b * NSEQ * DD;
    const float* Vb = V  + (size_t)b * NSEQ * CC;

    // ---- stage Q (scaled, tf32) into Ks region, then grab A-fragments ----
    const float scale = 0.17677669529663687f;   // 1/sqrt(32)
#pragma unroll
    for (int i = 0; i < 8; i++) {
        int l = tid + i * 256;
        int r = l >> 5, d = l & 31;
        Ks[r * KSTR + d] = __uint_as_float(f2tf(Qb[(size_t)r * DD + d] * scale));
    }
    if (tid < 64) { mrow[tid] = -INFINITY; lrow[tid] = 0.f; }
    __syncthreads();

    const int m0 = 16 * (w & 3);
    const int n0 = 32 * (w >> 2);
    uint32_t qa[4][4];
#pragma unroll
    for (int kc = 0; kc < 4; kc++) {
        qa[kc][0] = __float_as_uint(Ks[(m0 + g)     * KSTR + 8 * kc + t]);
        qa[kc][1] = __float_as_uint(Ks[(m0 + g + 8) * KSTR + 8 * kc + t]);
        qa[kc][2] = __float_as_uint(Ks[(m0 + g)     * KSTR + 8 * kc + t + 4]);
        qa[kc][3] = __float_as_uint(Ks[(m0 + g + 8) * KSTR + 8 * kc + t + 4]);
    }
    __syncthreads();

    // PV mapping
    const int R0 = 32 * (w & 1);
    const int C0 = 64 * (w >> 1);
    float oacc[2][8][4];
#pragma unroll
    for (int mb = 0; mb < 2; mb++)
#pragma unroll
        for (int nb = 0; nb < 8; nb++)
#pragma unroll
            for (int j = 0; j < 4; j++) oacc[mb][nb][j] = 0.f;

    for (int kt = 0; kt < NSEQ / 64; kt++) {
        // ---- load K tile (64x32) ----
#pragma unroll
        for (int i = 0; i < 8; i++) {
            int l = tid + i * 256;
            int r = l >> 5, d = l & 31;
            Ks[r * KSTR + d] = __uint_as_float(f2tf(Kb[((size_t)kt * 64 + r) * DD + d]));
        }
        // ---- load V tile (64x256) as float4, convert to tf32 ----
        const float4* Vg = (const float4*)(Vb + (size_t)kt * 64 * CC);
#pragma unroll
        for (int i = 0; i < 16; i++) {
            int l = tid + i * 256;
            int r = l >> 6, c4 = l & 63;
            float4 v = Vg[r * 64 + c4];
            float4 o;
            o.x = __uint_as_float(f2tf(v.x));
            o.y = __uint_as_float(f2tf(v.y));
            o.z = __uint_as_float(f2tf(v.z));
            o.w = __uint_as_float(f2tf(v.w));
            *(float4*)&Vs[r * VSTR + c4 * 4] = o;
        }
        __syncthreads();

        // ---- S = Q @ K^T (16x32 per warp) ----
        float c[4][4];
#pragma unroll
        for (int nb = 0; nb < 4; nb++)
#pragma unroll
            for (int j = 0; j < 4; j++) c[nb][j] = 0.f;

#pragma unroll
        for (int kc = 0; kc < 4; kc++) {
#pragma unroll
            for (int nb = 0; nb < 4; nb++) {
                uint32_t bf[2];
                bf[0] = __float_as_uint(Ks[(n0 + 8 * nb + g) * KSTR + 8 * kc + t]);
                bf[1] = __float_as_uint(Ks[(n0 + 8 * nb + g) * KSTR + 8 * kc + t + 4]);
                mma_tf32(c[nb], qa[kc], bf);
            }
        }
        // write raw scores to Ps
#pragma unroll
        for (int nb = 0; nb < 4; nb++) {
            *(float2*)&Ps[(m0 + g)     * PSTR + n0 + 8 * nb + 2 * t] = make_float2(c[nb][0], c[nb][1]);
            *(float2*)&Ps[(m0 + g + 8) * PSTR + n0 + 8 * nb + 2 * t] = make_float2(c[nb][2], c[nb][3]);
        }
        __syncthreads();

        // ---- online softmax: 4 threads per row (quad) ----
        {
            int r  = tid >> 2;
            int q4 = tid & 3;
            float* prow = &Ps[r * PSTR + q4 * 16];
            float s[16];
            *(float4*)&s[0]  = *(const float4*)&prow[0];
            *(float4*)&s[4]  = *(const float4*)&prow[4];
            *(float4*)&s[8]  = *(const float4*)&prow[8];
            *(float4*)&s[12] = *(const float4*)&prow[12];

            float mx = s[0];
#pragma unroll
            for (int j = 1; j < 16; j++) mx = fmaxf(mx, s[j]);
            mx = fmaxf(mx, __shfl_xor_sync(0xFFFFFFFFu, mx, 1));
            mx = fmaxf(mx, __shfl_xor_sync(0xFFFFFFFFu, mx, 2));

            float mo   = mrow[r];
            float mnew = fmaxf(mo, mx);
            float al   = __expf(mo - mnew);

            float lsum = 0.f;
#pragma unroll
            for (int j = 0; j < 16; j++) {
                s[j] = __expf(s[j] - mnew);
                lsum += s[j];
            }
            lsum += __shfl_xor_sync(0xFFFFFFFFu, lsum, 1);
            lsum += __shfl_xor_sync(0xFFFFFFFFu, lsum, 2);

#pragma unroll
            for (int j = 0; j < 16; j++) s[j] = __uint_as_float(f2tf(s[j]));
            *(float4*)&prow[0]  = *(float4*)&s[0];
            *(float4*)&prow[4]  = *(float4*)&s[4];
            *(float4*)&prow[8]  = *(float4*)&s[8];
            *(float4*)&prow[12] = *(float4*)&s[12];

            if (q4 == 0) {
                mrow[r] = mnew;
                lrow[r] = lrow[r] * al + lsum;
                arow[r] = al;
            }
        }
        __syncthreads();

        // ---- rescale accumulators, then O += P @ V ----
        float aL[2], aH[2];
        aL[0] = arow[R0 + g];      aH[0] = arow[R0 + g + 8];
        aL[1] = arow[R0 + 16 + g]; aH[1] = arow[R0 + 16 + g + 8];
#pragma unroll
        for (int mb = 0; mb < 2; mb++)
#pragma unroll
            for (int nb = 0; nb < 8; nb++) {
                oacc[mb][nb][0] *= aL[mb];
                oacc[mb][nb][1] *= aL[mb];
                oacc[mb][nb][2] *= aH[mb];
                oacc[mb][nb][3] *= aH[mb];
            }

#pragma unroll
        for (int kc = 0; kc < 8; kc++) {
            uint32_t pa[2][4];
#pragma unroll
            for (int mb = 0; mb < 2; mb++) {
                pa[mb][0] = __float_as_uint(Ps[(R0 + 16 * mb + g)     * PSTR + 8 * kc + t]);
                pa[mb][1] = __float_as_uint(Ps[(R0 + 16 * mb + g + 8) * PSTR + 8 * kc + t]);
                pa[mb][2] = __float_as_uint(Ps[(R0 + 16 * mb + g)     * PSTR + 8 * kc + t + 4]);
                pa[mb][3] = __float_as_uint(Ps[(R0 + 16 * mb + g + 8) * PSTR + 8 * kc + t + 4]);
            }
#pragma unroll
            for (int nb = 0; nb < 8; nb++) {
                uint32_t bf[2];
                bf[0] = __float_as_uint(Vs[(8 * kc + t)     * VSTR + C0 + 8 * nb + g]);
                bf[1] = __float_as_uint(Vs[(8 * kc + t + 4) * VSTR + C0 + 8 * nb + g]);
                mma_tf32(oacc[0][nb], pa[0], bf);
                mma_tf32(oacc[1][nb], pa[1], bf);
            }
        }
        __syncthreads();
    }

    // ---- epilogue: normalize by l, store ----
    float iL[2], iH[2];
    iL[0] = 1.f / lrow[R0 + g];      iH[0] = 1.f / lrow[R0 + g + 8];
    iL[1] = 1.f / lrow[R0 + 16 + g]; iH[1] = 1.f / lrow[R0 + 16 + g + 8];

    float* Ob = O + ((size_t)b * NSEQ + qb * 64) * CC;
#pragma unroll
    for (int mb = 0; mb < 2; mb++) {
        int rlo = R0 + 16 * mb + g;
        int rhi = rlo + 8;
#pragma unroll
        for (int nb = 0; nb < 8; nb++) {
            int col = C0 + 8 * nb + 2 * t;
            *(float2*)&Ob[(size_t)rlo * CC + col] =
                make_float2(oacc[mb][nb][0] * iL[mb], oacc[mb][nb][1] * iL[mb]);
            *(float2*)&Ob[(size_t)rhi * CC + col] =
                make_float2(oacc[mb][nb][2] * iH[mb], oacc[mb][nb][3] * iH[mb]);
        }
    }
}

// ---------------------------------------------------------------------------
extern "C" void kernel_launch(void* const* d_in, const int* in_sizes, int n_in,
                              void* d_out, int out_size)
{
    const float* x  = (const float*)d_in[0];
    const float* wq = (const float*)d_in[1];
    const float* bq = (const float*)d_in[2];
    const float* wk = (const float*)d_in[3];
    const float* bk = (const float*)d_in[4];
    const float* wv = (const float*)d_in[5];
    const float* bv = (const float*)d_in[6];
    const float* wo = (const float*)d_in[7];
    const float* bo = (const float*)d_in[8];
    float* out = (float*)d_out;

    float *qp, *kp, *vp, *ap;
    cudaGetSymbolAddress((void**)&qp, g_q);
    cudaGetSymbolAddress((void**)&kp, g_k);
    cudaGetSymbolAddress((void**)&vp, g_v);
    cudaGetSymbolAddress((void**)&ap, g_att);

    const int M = BB * NSEQ;   // 16384

    // Projections
    gemm_bias_kernel<<<dim3(1, M / 64), 256>>>(x, wq, bq, nullptr, qp, M, DD, CC);
    gemm_bias_kernel<<<dim3(1, M / 64), 256>>>(x, wk, bk, nullptr, kp, M, DD, CC);
    gemm_bias_kernel<<<dim3(CC / 64, M / 64), 256>>>(x, wv, bv, nullptr, vp, M, CC, CC);

    // Flash attention (tf32 tensor cores)
    size_t smem = FLASH_SMEM_FLOATS * sizeof(float);
    cudaFuncSetAttribute(flash_tc_kernel, cudaFuncAttributeMaxDynamicSharedMemorySize, (int)smem);
    flash_tc_kernel<<<dim3(NSEQ / 64, BB), 256, smem>>>(qp, kp, vp, ap);

    // Output projection + bias + residual -> d_out
    gemm_bias_kernel<<<dim3(CC / 64, M / 64), 256>>>(ap, wo, bo, x, out, M, CC, CC);
}

// round 3
// speedup vs baseline: 3.8614x; 1.3419x over previous
#include <cuda_runtime.h>
#include <cuda_bf16.h>
#include <math.h>
#include <stdint.h>

// Problem constants
#define BB 4
#define NSEQ 4096        // H*W
#define CC 256
#define DD 32

// Scratch (device globals)
__device__ __nv_bfloat16 g_q[BB * NSEQ * DD];
__device__ __nv_bfloat16 g_k[BB * NSEQ * DD];
__device__ __nv_bfloat16 g_v[BB * NSEQ * CC];
__device__ float         g_att[BB * NSEQ * CC];

// ---------------------------------------------------------------------------
// helpers
// ---------------------------------------------------------------------------
__device__ __forceinline__ uint32_t smaddr(const void* p) {
    return (uint32_t)__cvta_generic_to_shared(p);
}
__device__ __forceinline__ uint4 ldsm_x4(const void* p) {
    uint4 r; uint32_t a = smaddr(p);
    asm volatile("ldmatrix.sync.aligned.m8n8.x4.shared.b16 {%0,%1,%2,%3}, [%4];"
                 : "=r"(r.x), "=r"(r.y), "=r"(r.z), "=r"(r.w) : "r"(a));
    return r;
}
__device__ __forceinline__ uint4 ldsm_x4t(const void* p) {
    uint4 r; uint32_t a = smaddr(p);
    asm volatile("ldmatrix.sync.aligned.m8n8.x4.trans.shared.b16 {%0,%1,%2,%3}, [%4];"
                 : "=r"(r.x), "=r"(r.y), "=r"(r.z), "=r"(r.w) : "r"(a));
    return r;
}
__device__ __forceinline__ void mma_bf16(float* c, const uint4& a, uint32_t b0, uint32_t b1) {
    asm volatile(
        "mma.sync.aligned.m16n8k16.row.col.f32.bf16.bf16.f32 "
        "{%0,%1,%2,%3}, {%4,%5,%6,%7}, {%8,%9}, {%0,%1,%2,%3};"
        : "+f"(c[0]), "+f"(c[1]), "+f"(c[2]), "+f"(c[3])
        : "r"(a.x), "r"(a.y), "r"(a.z), "r"(a.w), "r"(b0), "r"(b1));
}
__device__ __forceinline__ void mma_tf32(float* c, const uint32_t* a, const uint32_t* b) {
    asm volatile(
        "mma.sync.aligned.m16n8k8.row.col.f32.tf32.tf32.f32 "
        "{%0,%1,%2,%3}, {%4,%5,%6,%7}, {%8,%9}, {%0,%1,%2,%3};"
        : "+f"(c[0]), "+f"(c[1]), "+f"(c[2]), "+f"(c[3])
        : "r"(a[0]), "r"(a[1]), "r"(a[2]), "r"(a[3]), "r"(b[0]), "r"(b[1]));
}
__device__ __forceinline__ uint32_t f2tf(float f) {
    uint32_t u; asm("cvt.rna.tf32.f32 %0, %1;" : "=r"(u) : "f"(f)); return u;
}
__device__ __forceinline__ float fexp2(float x) {
    float y; asm("ex2.approx.ftz.f32 %0, %1;" : "=f"(y) : "f"(x)); return y;
}
__device__ __forceinline__ uint32_t bf2pack(float lo, float hi) {
    uint32_t u; asm("cvt.rn.bf16x2.f32 %0, %1, %2;" : "=r"(u) : "f"(hi), "f"(lo)); return u;
}

// ---------------------------------------------------------------------------
// TF32 tensor GEMM: C[M,N] = A[M,K] @ W[K,N] + bias (+ res). BM=128 BN=64 BK=16.
// 256 threads, 8 warps; warp = 32x32 (wm=w&3 rows, wn=w>>2 cols).
// ---------------------------------------------------------------------------
#define ASTR 20
#define WSTR 72

template <typename OutT>
__global__ __launch_bounds__(256) void gemm_tf32_kernel(
    const float* __restrict__ A, const float* __restrict__ W,
    const float* __restrict__ bias, const float* __restrict__ res,
    OutT* __restrict__ Cm, int M, int N, int K)
{
    __shared__ float As[128 * ASTR];
    __shared__ float Ws[16 * WSTR];

    const int tid  = threadIdx.x;
    const int lane = tid & 31;
    const int w    = tid >> 5;
    const int g    = lane >> 2;
    const int t    = lane & 3;
    const int wm   = w & 3;
    const int wn   = w >> 2;

    const int m0 = blockIdx.y * 128;
    const int n0 = blockIdx.x * 64;

    float c[2][4][4];
#pragma unroll
    for (int mb = 0; mb < 2; mb++)
#pragma unroll
        for (int nb = 0; nb < 4; nb++)
#pragma unroll
            for (int j = 0; j < 4; j++) c[mb][nb][j] = 0.f;

    for (int k0 = 0; k0 < K; k0 += 16) {
        // A tile: 128x16
#pragma unroll
        for (int i = 0; i < 2; i++) {
            int idx = tid + i * 256;
            int r = idx >> 2, c4 = idx & 3;
            float4 v = *(const float4*)&A[(size_t)(m0 + r) * K + k0 + c4 * 4];
            float4 o;
            o.x = __uint_as_float(f2tf(v.x)); o.y = __uint_as_float(f2tf(v.y));
            o.z = __uint_as_float(f2tf(v.z)); o.w = __uint_as_float(f2tf(v.w));
            *(float4*)&As[r * ASTR + c4 * 4] = o;
        }
        // W tile: 16x64
        {
            int r = tid >> 4, c4 = tid & 15;
            int col = n0 + c4 * 4;
            float4 o;
            if (col + 3 < N) {
                float4 v = *(const float4*)&W[(size_t)(k0 + r) * N + col];
                o.x = __uint_as_float(f2tf(v.x)); o.y = __uint_as_float(f2tf(v.y));
                o.z = __uint_as_float(f2tf(v.z)); o.w = __uint_as_float(f2tf(v.w));
            } else {
                o = make_float4(0.f, 0.f, 0.f, 0.f);
            }
            *(float4*)&Ws[r * WSTR + c4 * 4] = o;
        }
        __syncthreads();

#pragma unroll
        for (int kc = 0; kc < 2; kc++) {
            int kk = kc * 8;
            uint32_t a[2][4];
#pragma unroll
            for (int mb = 0; mb < 2; mb++) {
                int rbase = wm * 32 + mb * 16;
                a[mb][0] = __float_as_uint(As[(rbase + g)     * ASTR + kk + t]);
                a[mb][1] = __float_as_uint(As[(rbase + g + 8) * ASTR + kk + t]);
                a[mb][2] = __float_as_uint(As[(rbase + g)     * ASTR + kk + t + 4]);
                a[mb][3] = __float_as_uint(As[(rbase + g + 8) * ASTR + kk + t + 4]);
            }
#pragma unroll
            for (int nb = 0; nb < 4; nb++) {
                uint32_t b[2];
                int col = wn * 32 + nb * 8 + g;
                b[0] = __float_as_uint(Ws[(kk + t)     * WSTR + col]);
                b[1] = __float_as_uint(Ws[(kk + t + 4) * WSTR + col]);
                mma_tf32(c[0][nb], a[0], b);
                mma_tf32(c[1][nb], a[1], b);
            }
        }
        __syncthreads();
    }

    // epilogue
#pragma unroll
    for (int mb = 0; mb < 2; mb++) {
        int rlo = m0 + wm * 32 + mb * 16 + g;
        int rhi = rlo + 8;
#pragma unroll
        for (int nb = 0; nb < 4; nb++) {
            int col = n0 + wn * 32 + nb * 8 + 2 * t;
            if (col < N) {
                float b0 = bias[col], b1 = bias[col + 1];
                float v00 = c[mb][nb][0] + b0, v01 = c[mb][nb][1] + b1;
                float v10 = c[mb][nb][2] + b0, v11 = c[mb][nb][3] + b1;
                if (res) {
                    v00 += res[(size_t)rlo * N + col]; v01 += res[(size_t)rlo * N + col + 1];
                    v10 += res[(size_t)rhi * N + col]; v11 += res[(size_t)rhi * N + col + 1];
                }
                if (sizeof(OutT) == 4) {
                    *(float2*)&((float*)Cm)[(size_t)rlo * N + col] = make_float2(v00, v01);
                    *(float2*)&((float*)Cm)[(size_t)rhi * N + col] = make_float2(v10, v11);
                } else {
                    ((uint32_t*)Cm)[((size_t)rlo * N + col) >> 1] = bf2pack(v00, v01);
                    ((uint32_t*)Cm)[((size_t)rhi * N + col) >> 1] = bf2pack(v10, v11);
                }
            }
        }
    }
}

// ---------------------------------------------------------------------------
// bf16 tensor-core flash attention. 256 threads / 8 warps. BM=BN=64.
// S-phase : warps 0-3, warp w -> rows [16w,16w+16) x all 64 cols, softmax in regs.
// PV-phase: all 8 warps, warp w -> rows [32*(w&1),+32) x cols [64*(w>>1),+64).
// smem (bf16 strides): Ks 64x40, Vs 64x264, Ps 64x88, + m/l/alpha fp32.
// ---------------------------------------------------------------------------
#define KSTRH 40
#define VSTRH 264
#define PSTRH 88
#define FLASH_SMEM_BYTES (64*KSTRH*2 + 64*VSTRH*2 + 64*PSTRH*2 + 3*64*4)
#define SCL 0.25506806f   // log2(e)/sqrt(32)

__global__ __launch_bounds__(256, 2) void flash_bf16_kernel(
    const __nv_bfloat16* __restrict__ Q, const __nv_bfloat16* __restrict__ Kg,
    const __nv_bfloat16* __restrict__ V, float* __restrict__ O)
{
    extern __shared__ char smc[];
    __nv_bfloat16* Ks = (__nv_bfloat16*)smc;
    __nv_bfloat16* Vs = Ks + 64 * KSTRH;
    __nv_bfloat16* Ps = Vs + 64 * VSTRH;
    float* mrow = (float*)(smc + (64*KSTRH + 64*VSTRH + 64*PSTRH) * 2);
    float* lrow = mrow + 64;
    float* arow = lrow + 64;

    const int tid  = threadIdx.x;
    const int lane = tid & 31;
    const int w    = tid >> 5;
    const int g    = lane >> 2;
    const int t    = lane & 3;

    const int qb = blockIdx.x;
    const int b  = blockIdx.y;

    const __nv_bfloat16* Qb = Q  + ((size_t)b * NSEQ + qb * 64) * DD;
    const __nv_bfloat16* Kb = Kg + (size_t)b * NSEQ * DD;
    const __nv_bfloat16* Vb = V  + (size_t)b * NSEQ * CC;

    // ldmatrix lane offsets
    const int roffA = (lane & 7) + ((lane >> 3) & 1) * 8;   // A-frag & V-trans rows
    const int coffA = ((lane >> 4) & 1) * 8;
    const int roffB = (lane & 7) + ((lane >> 4) & 1) * 8;   // K non-trans B rows
    const int coffB = ((lane >> 3) & 1) * 8;

    // ---- stage Q (bf16) into Ps region, grab A-fragments (warps 0-3) ----
#pragma unroll
    for (int i = 0; i < 4; i++) {
        int l = tid + i * 256;
        int r = l >> 4, c = l & 15;
        ((uint32_t*)Ps)[r * (PSTRH/2) + c] = ((const uint32_t*)Qb)[r * 16 + c];
    }
    if (tid < 64) { mrow[tid] = -INFINITY; lrow[tid] = 0.f; }
    __syncthreads();

    const int m0 = 16 * (w & 3);
    uint4 qa[2];
    if (w < 4) {
#pragma unroll
        for (int kc = 0; kc < 2; kc++)
            qa[kc] = ldsm_x4(&Ps[(m0 + roffA) * PSTRH + kc * 16 + coffA]);
    }

    const int R0 = 32 * (w & 1);
    const int C0 = 64 * (w >> 1);
    float oacc[2][8][4];
#pragma unroll
    for (int mb = 0; mb < 2; mb++)
#pragma unroll
        for (int nb = 0; nb < 8; nb++)
#pragma unroll
            for (int j = 0; j < 4; j++) oacc[mb][nb][j] = 0.f;

    for (int kt = 0; kt < NSEQ / 64; kt++) {
        __syncthreads();   // protect Ks/Vs (prev PV done), Ps qa-read done (kt==0)
        // ---- load K tile (64x32 bf16) ----
#pragma unroll
        for (int i = 0; i < 4; i++) {
            int l = tid + i * 256;
            int r = l >> 4, c = l & 15;
            ((uint32_t*)Ks)[r * (KSTRH/2) + c] =
                ((const uint32_t*)Kb)[((size_t)kt * 64 + r) * 16 + c];
        }
        // ---- load V tile (64x256 bf16) ----
#pragma unroll
        for (int i = 0; i < 8; i++) {
            int l = tid + i * 256;
            int r = l >> 5, c4 = l & 31;
            ((uint4*)Vs)[r * (VSTRH/8) + c4] =
                ((const uint4*)Vb)[((size_t)kt * 64 + r) * 32 + c4];
        }
        __syncthreads();

        // ---- S phase: warps 0-3, 16 rows x 64 cols each ----
        if (w < 4) {
            float c[8][4];
#pragma unroll
            for (int nb = 0; nb < 8; nb++)
#pragma unroll
                for (int j = 0; j < 4; j++) c[nb][j] = 0.f;

#pragma unroll
            for (int kc = 0; kc < 2; kc++) {
#pragma unroll
                for (int nbp = 0; nbp < 8; nbp += 2) {
                    uint4 bb = ldsm_x4(&Ks[(nbp * 8 + roffB) * KSTRH + kc * 16 + coffB]);
                    mma_bf16(c[nbp],     qa[kc], bb.x, bb.y);
                    mma_bf16(c[nbp + 1], qa[kc], bb.z, bb.w);
                }
            }

            // scale into log2-units
#pragma unroll
            for (int nb = 0; nb < 8; nb++)
#pragma unroll
                for (int j = 0; j < 4; j++) c[nb][j] *= SCL;

            // row maxes (rows m0+g, m0+g+8)
            float mxlo = -INFINITY, mxhi = -INFINITY;
#pragma unroll
            for (int nb = 0; nb < 8; nb++) {
                mxlo = fmaxf(mxlo, fmaxf(c[nb][0], c[nb][1]));
                mxhi = fmaxf(mxhi, fmaxf(c[nb][2], c[nb][3]));
            }
            mxlo = fmaxf(mxlo, __shfl_xor_sync(0xFFFFFFFFu, mxlo, 1));
            mxlo = fmaxf(mxlo, __shfl_xor_sync(0xFFFFFFFFu, mxlo, 2));
            mxhi = fmaxf(mxhi, __shfl_xor_sync(0xFFFFFFFFu, mxhi, 1));
            mxhi = fmaxf(mxhi, __shfl_xor_sync(0xFFFFFFFFu, mxhi, 2));

            float molo = mrow[m0 + g], mohi = mrow[m0 + g + 8];
            float mnlo = fmaxf(molo, mxlo), mnhi = fmaxf(mohi, mxhi);
            float allo = fexp2(molo - mnlo), alhi = fexp2(mohi - mnhi);

            float lslo = 0.f, lshi = 0.f;
#pragma unroll
            for (int nb = 0; nb < 8; nb++) {
                c[nb][0] = fexp2(c[nb][0] - mnlo);
                c[nb][1] = fexp2(c[nb][1] - mnlo);
                c[nb][2] = fexp2(c[nb][2] - mnhi);
                c[nb][3] = fexp2(c[nb][3] - mnhi);
                lslo += c[nb][0] + c[nb][1];
                lshi += c[nb][2] + c[nb][3];
            }
            lslo += __shfl_xor_sync(0xFFFFFFFFu, lslo, 1);
            lslo += __shfl_xor_sync(0xFFFFFFFFu, lslo, 2);
            lshi += __shfl_xor_sync(0xFFFFFFFFu, lshi, 1);
            lshi += __shfl_xor_sync(0xFFFFFFFFu, lshi, 2);

            if (t == 0) {
                mrow[m0 + g] = mnlo;
                lrow[m0 + g] = lrow[m0 + g] * allo + lslo;
                arow[m0 + g] = allo;
                mrow[m0 + g + 8] = mnhi;
                lrow[m0 + g + 8] = lrow[m0 + g + 8] * alhi + lshi;
                arow[m0 + g + 8] = alhi;
            }

            // store P (bf16)
            uint32_t* Pu = (uint32_t*)Ps;
#pragma unroll
            for (int nb = 0; nb < 8; nb++) {
                Pu[(m0 + g)     * (PSTRH/2) + nb * 4 + t] = bf2pack(c[nb][0], c[nb][1]);
                Pu[(m0 + g + 8) * (PSTRH/2) + nb * 4 + t] = bf2pack(c[nb][2], c[nb][3]);
            }
        }
        __syncthreads();

        // ---- PV phase: all warps ----
        float aL[2], aH[2];
        aL[0] = arow[R0 + g];      aH[0] = arow[R0 + g + 8];
        aL[1] = arow[R0 + 16 + g]; aH[1] = arow[R0 + 16 + g + 8];
#pragma unroll
        for (int mb = 0; mb < 2; mb++)
#pragma unroll
            for (int nb = 0; nb < 8; nb++) {
                oacc[mb][nb][0] *= aL[mb];
                oacc[mb][nb][1] *= aL[mb];
                oacc[mb][nb][2] *= aH[mb];
                oacc[mb][nb][3] *= aH[mb];
            }

#pragma unroll
        for (int kc = 0; kc < 4; kc++) {
            uint4 pa0 = ldsm_x4(&Ps[(R0 + roffA)      * PSTRH + kc * 16 + coffA]);
            uint4 pa1 = ldsm_x4(&Ps[(R0 + 16 + roffA) * PSTRH + kc * 16 + coffA]);
#pragma unroll
            for (int nbp = 0; nbp < 8; nbp += 2) {
                uint4 bb = ldsm_x4t(&Vs[(kc * 16 + roffA) * VSTRH + C0 + nbp * 8 + coffA]);
                mma_bf16(oacc[0][nbp],     pa0, bb.x, bb.y);
                mma_bf16(oacc[0][nbp + 1], pa0, bb.z, bb.w);
                mma_bf16(oacc[1][nbp],     pa1, bb.x, bb.y);
                mma_bf16(oacc[1][nbp + 1], pa1, bb.z, bb.w);
            }
        }
    }
    __syncthreads();

    // ---- epilogue ----
    float iL[2], iH[2];
    iL[0] = 1.f / lrow[R0 + g];      iH[0] = 1.f / lrow[R0 + g + 8];
    iL[1] = 1.f / lrow[R0 + 16 + g]; iH[1] = 1.f / lrow[R0 + 16 + g + 8];

    float* Ob = O + ((size_t)b * NSEQ + qb * 64) * CC;
#pragma unroll
    for (int mb = 0; mb < 2; mb++) {
        int rlo = R0 + 16 * mb + g;
        int rhi = rlo + 8;
#pragma unroll
        for (int nb = 0; nb < 8; nb++) {
            int col = C0 + 8 * nb + 2 * t;
            *(float2*)&Ob[(size_t)rlo * CC + col] =
                make_float2(oacc[mb][nb][0] * iL[mb], oacc[mb][nb][1] * iL[mb]);
            *(float2*)&Ob[(size_t)rhi * CC + col] =
                make_float2(oacc[mb][nb][2] * iH[mb], oacc[mb][nb][3] * iH[mb]);
        }
    }
}

// ---------------------------------------------------------------------------
extern "C" void kernel_launch(void* const* d_in, const int* in_sizes, int n_in,
                              void* d_out, int out_size)
{
    const float* x  = (const float*)d_in[0];
    const float* wq = (const float*)d_in[1];
    const float* bq = (const float*)d_in[2];
    const float* wk = (const float*)d_in[3];
    const float* bk = (const float*)d_in[4];
    const float* wv = (const float*)d_in[5];
    const float* bv = (const float*)d_in[6];
    const float* wo = (const float*)d_in[7];
    const float* bo = (const float*)d_in[8];
    float* out = (float*)d_out;

    __nv_bfloat16 *qp, *kp, *vp;
    float* ap;
    cudaGetSymbolAddress((void**)&qp, g_q);
    cudaGetSymbolAddress((void**)&kp, g_k);
    cudaGetSymbolAddress((void**)&vp, g_v);
    cudaGetSymbolAddress((void**)&ap, g_att);

    const int M = BB * NSEQ;   // 16384

    // Projections (tf32 tensor GEMM; q/k/v emitted as bf16)
    gemm_tf32_kernel<__nv_bfloat16><<<dim3(1, M / 128), 256>>>(x, wq, bq, nullptr, qp, M, DD, CC);
    gemm_tf32_kernel<__nv_bfloat16><<<dim3(1, M / 128), 256>>>(x, wk, bk, nullptr, kp, M, DD, CC);
    gemm_tf32_kernel<__nv_bfloat16><<<dim3(CC / 64, M / 128), 256>>>(x, wv, bv, nullptr, vp, M, CC, CC);

    // Flash attention (bf16 tensor cores)
    cudaFuncSetAttribute(flash_bf16_kernel, cudaFuncAttributeMaxDynamicSharedMemorySize,
                         FLASH_SMEM_BYTES);
    flash_bf16_kernel<<<dim3(NSEQ / 64, BB), 256, FLASH_SMEM_BYTES>>>(qp, kp, vp, ap);

    // Output projection + bias + residual -> d_out (fp32)
    gemm_tf32_kernel<float><<<dim3(CC / 64, M / 128), 256>>>(ap, wo, bo, x, out, M, CC, CC);
}

// round 4
// speedup vs baseline: 6.5873x; 1.7060x over previous
#include <cuda_runtime.h>
#include <cuda_bf16.h>
#include <math.h>
#include <stdint.h>

// Problem constants
#define BB 4
#define NSEQ 4096        // H*W
#define CC 256
#define DD 32

// Scratch (device globals)
__device__ __nv_bfloat16 g_q[BB * NSEQ * DD];
__device__ __nv_bfloat16 g_k[BB * NSEQ * DD];
__device__ __nv_bfloat16 g_v[BB * NSEQ * CC];
__device__ float         g_att[BB * NSEQ * CC];

// ---------------------------------------------------------------------------
// helpers
// ---------------------------------------------------------------------------
__device__ __forceinline__ uint32_t smaddr(const void* p) {
    return (uint32_t)__cvta_generic_to_shared(p);
}
__device__ __forceinline__ uint4 ldsm_x4(const void* p) {
    uint4 r; uint32_t a = smaddr(p);
    asm volatile("ldmatrix.sync.aligned.m8n8.x4.shared.b16 {%0,%1,%2,%3}, [%4];"
                 : "=r"(r.x), "=r"(r.y), "=r"(r.z), "=r"(r.w) : "r"(a));
    return r;
}
__device__ __forceinline__ uint4 ldsm_x4t(const void* p) {
    uint4 r; uint32_t a = smaddr(p);
    asm volatile("ldmatrix.sync.aligned.m8n8.x4.trans.shared.b16 {%0,%1,%2,%3}, [%4];"
                 : "=r"(r.x), "=r"(r.y), "=r"(r.z), "=r"(r.w) : "r"(a));
    return r;
}
__device__ __forceinline__ void mma_bf16(float* c, const uint4& a, uint32_t b0, uint32_t b1) {
    asm volatile(
        "mma.sync.aligned.m16n8k16.row.col.f32.bf16.bf16.f32 "
        "{%0,%1,%2,%3}, {%4,%5,%6,%7}, {%8,%9}, {%0,%1,%2,%3};"
        : "+f"(c[0]), "+f"(c[1]), "+f"(c[2]), "+f"(c[3])
        : "r"(a.x), "r"(a.y), "r"(a.z), "r"(a.w), "r"(b0), "r"(b1));
}
__device__ __forceinline__ void mma_tf32(float* c, const uint32_t* a, const uint32_t* b) {
    asm volatile(
        "mma.sync.aligned.m16n8k8.row.col.f32.tf32.tf32.f32 "
        "{%0,%1,%2,%3}, {%4,%5,%6,%7}, {%8,%9}, {%0,%1,%2,%3};"
        : "+f"(c[0]), "+f"(c[1]), "+f"(c[2]), "+f"(c[3])
        : "r"(a[0]), "r"(a[1]), "r"(a[2]), "r"(a[3]), "r"(b[0]), "r"(b[1]));
}
__device__ __forceinline__ uint32_t f2tf(float f) {
    uint32_t u; asm("cvt.rna.tf32.f32 %0, %1;" : "=r"(u) : "f"(f)); return u;
}
__device__ __forceinline__ float fexp2(float x) {
    float y; asm("ex2.approx.ftz.f32 %0, %1;" : "=f"(y) : "f"(x)); return y;
}
__device__ __forceinline__ uint32_t bf2pack(float lo, float hi) {
    uint32_t u; asm("cvt.rn.bf16x2.f32 %0, %1, %2;" : "=r"(u) : "f"(hi), "f"(lo)); return u;
}
__device__ __forceinline__ void cp16(uint32_t dst, const void* src) {
    asm volatile("cp.async.cg.shared.global [%0], [%1], 16;" :: "r"(dst), "l"(src));
}
__device__ __forceinline__ void cp_commit() {
    asm volatile("cp.async.commit_group;");
}

// ---------------------------------------------------------------------------
// TF32 tensor GEMM: C[M,N] = (A@W + bias) * outscale (+ res). BM=128 BN=64 BK=16.
// ---------------------------------------------------------------------------
#define ASTR 20
#define WSTR 72

template <typename OutT>
__global__ __launch_bounds__(256) void gemm_tf32_kernel(
    const float* __restrict__ A, const float* __restrict__ W,
    const float* __restrict__ bias, const float* __restrict__ res,
    OutT* __restrict__ Cm, int M, int N, int K, float outscale)
{
    __shared__ float As[128 * ASTR];
    __shared__ float Ws[16 * WSTR];

    const int tid  = threadIdx.x;
    const int lane = tid & 31;
    const int w    = tid >> 5;
    const int g    = lane >> 2;
    const int t    = lane & 3;
    const int wm   = w & 3;
    const int wn   = w >> 2;

    const int m0 = blockIdx.y * 128;
    const int n0 = blockIdx.x * 64;

    float c[2][4][4];
#pragma unroll
    for (int mb = 0; mb < 2; mb++)
#pragma unroll
        for (int nb = 0; nb < 4; nb++)
#pragma unroll
            for (int j = 0; j < 4; j++) c[mb][nb][j] = 0.f;

    for (int k0 = 0; k0 < K; k0 += 16) {
#pragma unroll
        for (int i = 0; i < 2; i++) {
            int idx = tid + i * 256;
            int r = idx >> 2, c4 = idx & 3;
            float4 v = *(const float4*)&A[(size_t)(m0 + r) * K + k0 + c4 * 4];
            float4 o;
            o.x = __uint_as_float(f2tf(v.x)); o.y = __uint_as_float(f2tf(v.y));
            o.z = __uint_as_float(f2tf(v.z)); o.w = __uint_as_float(f2tf(v.w));
            *(float4*)&As[r * ASTR + c4 * 4] = o;
        }
        {
            int r = tid >> 4, c4 = tid & 15;
            int col = n0 + c4 * 4;
            float4 o;
            if (col + 3 < N) {
                float4 v = *(const float4*)&W[(size_t)(k0 + r) * N + col];
                o.x = __uint_as_float(f2tf(v.x)); o.y = __uint_as_float(f2tf(v.y));
                o.z = __uint_as_float(f2tf(v.z)); o.w = __uint_as_float(f2tf(v.w));
            } else {
                o = make_float4(0.f, 0.f, 0.f, 0.f);
            }
            *(float4*)&Ws[r * WSTR + c4 * 4] = o;
        }
        __syncthreads();

#pragma unroll
        for (int kc = 0; kc < 2; kc++) {
            int kk = kc * 8;
            uint32_t a[2][4];
#pragma unroll
            for (int mb = 0; mb < 2; mb++) {
                int rbase = wm * 32 + mb * 16;
                a[mb][0] = __float_as_uint(As[(rbase + g)     * ASTR + kk + t]);
                a[mb][1] = __float_as_uint(As[(rbase + g + 8) * ASTR + kk + t]);
                a[mb][2] = __float_as_uint(As[(rbase + g)     * ASTR + kk + t + 4]);
                a[mb][3] = __float_as_uint(As[(rbase + g + 8) * ASTR + kk + t + 4]);
            }
#pragma unroll
            for (int nb = 0; nb < 4; nb++) {
                uint32_t b[2];
                int col = wn * 32 + nb * 8 + g;
                b[0] = __float_as_uint(Ws[(kk + t)     * WSTR + col]);
                b[1] = __float_as_uint(Ws[(kk + t + 4) * WSTR + col]);
                mma_tf32(c[0][nb], a[0], b);
                mma_tf32(c[1][nb], a[1], b);
            }
        }
        __syncthreads();
    }

#pragma unroll
    for (int mb = 0; mb < 2; mb++) {
        int rlo = m0 + wm * 32 + mb * 16 + g;
        int rhi = rlo + 8;
#pragma unroll
        for (int nb = 0; nb < 4; nb++) {
            int col = n0 + wn * 32 + nb * 8 + 2 * t;
            if (col < N) {
                float b0 = bias[col], b1 = bias[col + 1];
                float v00 = (c[mb][nb][0] + b0) * outscale, v01 = (c[mb][nb][1] + b1) * outscale;
                float v10 = (c[mb][nb][2] + b0) * outscale, v11 = (c[mb][nb][3] + b1) * outscale;
                if (res) {
                    v00 += res[(size_t)rlo * N + col]; v01 += res[(size_t)rlo * N + col + 1];
                    v10 += res[(size_t)rhi * N + col]; v11 += res[(size_t)rhi * N + col + 1];
                }
                if (sizeof(OutT) == 4) {
                    *(float2*)&((float*)Cm)[(size_t)rlo * N + col] = make_float2(v00, v01);
                    *(float2*)&((float*)Cm)[(size_t)rhi * N + col] = make_float2(v10, v11);
                } else {
                    ((uint32_t*)Cm)[((size_t)rlo * N + col) >> 1] = bf2pack(v00, v01);
                    ((uint32_t*)Cm)[((size_t)rhi * N + col) >> 1] = bf2pack(v10, v11);
                }
            }
        }
    }
}

// ---------------------------------------------------------------------------
// Fused-register bf16 flash attention. 256 threads / 8 warps.
// BM=128 (warp w owns rows 16w..16w+16 for S, softmax AND PV), BN=64.
// P lives in registers (S C-frag == PV A-frag). Softmax state in registers.
// K/V double-buffered via cp.async. Q A-frags loaded straight from gmem.
// Q is pre-scaled by log2(e)/sqrt(D) at projection time.
// smem: K[2][64*40] V[2][64*264] (bf16).
// ---------------------------------------------------------------------------
#define KSTRH 40
#define VSTRH 264
#define KSTAGE (64 * KSTRH)            // bf16 elems per K stage
#define VSTAGE (64 * VSTRH)
#define FLASH_SMEM_BYTES ((2 * KSTAGE + 2 * VSTAGE) * 2)

__global__ __launch_bounds__(256) void flash_fused_kernel(
    const __nv_bfloat16* __restrict__ Q, const __nv_bfloat16* __restrict__ Kg,
    const __nv_bfloat16* __restrict__ V, float* __restrict__ O)
{
    extern __shared__ __nv_bfloat16 sm[];
    __nv_bfloat16* Ks0 = sm;                    // stage 0/1 K
    __nv_bfloat16* Vs0 = sm + 2 * KSTAGE;       // stage 0/1 V

    const int tid  = threadIdx.x;
    const int lane = tid & 31;
    const int w    = tid >> 5;
    const int g    = lane >> 2;
    const int t    = lane & 3;

    const int qb = blockIdx.x;   // 0..31  (128 rows each)
    const int b  = blockIdx.y;

    const __nv_bfloat16* Qb = Q  + ((size_t)b * NSEQ + qb * 128 + 16 * w) * DD;
    const __nv_bfloat16* Kb = Kg + (size_t)b * NSEQ * DD;
    const __nv_bfloat16* Vb = V  + (size_t)b * NSEQ * CC;

    // ldmatrix lane offsets
    const int roffA = (lane & 7) + ((lane >> 3) & 1) * 8;
    const int coffA = ((lane >> 4) & 1) * 8;
    const int roffB = (lane & 7) + ((lane >> 4) & 1) * 8;
    const int coffB = ((lane >> 3) & 1) * 8;

    // per-thread K-load slice: 64x32 bf16 = 256 x 16B; r=tid>>2, c=tid&3
    const int kr = tid >> 2, kc16 = tid & 3;
    // per-thread V-load slices
    // issue tile 0 loads
    {
        uint32_t kdst = smaddr(&Ks0[kr * KSTRH + kc16 * 8]);
        cp16(kdst, &Kb[(size_t)kr * DD + kc16 * 8]);
#pragma unroll
        for (int i = 0; i < 8; i++) {
            int l = tid + i * 256;
            int r = l >> 5, c = l & 31;
            cp16(smaddr(&Vs0[r * VSTRH + c * 8]), &Vb[(size_t)r * CC + c * 8]);
        }
        cp_commit();
    }

    // Q A-fragments straight from gmem (layout == mma A-frag)
    uint4 qa[2];
#pragma unroll
    for (int kc = 0; kc < 2; kc++) {
        qa[kc].x = *(const uint32_t*)&Qb[(size_t)g       * DD + kc * 16 + 2 * t];
        qa[kc].y = *(const uint32_t*)&Qb[(size_t)(g + 8) * DD + kc * 16 + 2 * t];
        qa[kc].z = *(const uint32_t*)&Qb[(size_t)g       * DD + kc * 16 + 8 + 2 * t];
        qa[kc].w = *(const uint32_t*)&Qb[(size_t)(g + 8) * DD + kc * 16 + 8 + 2 * t];
    }

    // softmax running state (rows 16w+g, 16w+g+8)
    float mlo = -INFINITY, mhi = -INFINITY, llo = 0.f, lhi = 0.f;

    float oacc[32][4];
#pragma unroll
    for (int nb = 0; nb < 32; nb++)
#pragma unroll
        for (int j = 0; j < 4; j++) oacc[nb][j] = 0.f;

    const int NT = NSEQ / 64;   // 64 tiles
    for (int kt = 0; kt < NT; kt++) {
        const int s = kt & 1;
        __nv_bfloat16* Ks = Ks0 + s * KSTAGE;
        __nv_bfloat16* Vs = Vs0 + s * VSTAGE;

        __syncthreads();   // everyone finished compute on stage s^1 (tile kt-1)

        if (kt + 1 < NT) {
            __nv_bfloat16* Kn = Ks0 + (s ^ 1) * KSTAGE;
            __nv_bfloat16* Vn = Vs0 + (s ^ 1) * VSTAGE;
            const __nv_bfloat16* Kgp = Kb + (size_t)(kt + 1) * 64 * DD;
            const __nv_bfloat16* Vgp = Vb + (size_t)(kt + 1) * 64 * CC;
            cp16(smaddr(&Kn[kr * KSTRH + kc16 * 8]), &Kgp[(size_t)kr * DD + kc16 * 8]);
#pragma unroll
            for (int i = 0; i < 8; i++) {
                int l = tid + i * 256;
                int r = l >> 5, c = l & 31;
                cp16(smaddr(&Vn[r * VSTRH + c * 8]), &Vgp[(size_t)r * CC + c * 8]);
            }
            cp_commit();
            asm volatile("cp.async.wait_group 1;");
        } else {
            asm volatile("cp.async.wait_group 0;");
        }
        __syncthreads();   // tile kt data visible to all

        // ---- S = Q @ K^T : 16 rows x 64 cols, scores already in log2 units ----
        uint4 prq[4];
        float alo, ahi;
        {
            float c[8][4];
#pragma unroll
            for (int nb = 0; nb < 8; nb++)
#pragma unroll
                for (int j = 0; j < 4; j++) c[nb][j] = 0.f;

#pragma unroll
            for (int kc = 0; kc < 2; kc++) {
#pragma unroll
                for (int nbp = 0; nbp < 8; nbp += 2) {
                    uint4 bb = ldsm_x4(&Ks[(nbp * 8 + roffB) * KSTRH + kc * 16 + coffB]);
                    mma_bf16(c[nbp],     qa[kc], bb.x, bb.y);
                    mma_bf16(c[nbp + 1], qa[kc], bb.z, bb.w);
                }
            }

            // row max
            float mxlo = -INFINITY, mxhi = -INFINITY;
#pragma unroll
            for (int nb = 0; nb < 8; nb++) {
                mxlo = fmaxf(mxlo, fmaxf(c[nb][0], c[nb][1]));
                mxhi = fmaxf(mxhi, fmaxf(c[nb][2], c[nb][3]));
            }
            mxlo = fmaxf(mxlo, __shfl_xor_sync(0xFFFFFFFFu, mxlo, 1));
            mxlo = fmaxf(mxlo, __shfl_xor_sync(0xFFFFFFFFu, mxlo, 2));
            mxhi = fmaxf(mxhi, __shfl_xor_sync(0xFFFFFFFFu, mxhi, 1));
            mxhi = fmaxf(mxhi, __shfl_xor_sync(0xFFFFFFFFu, mxhi, 2));

            float mnlo = fmaxf(mlo, mxlo), mnhi = fmaxf(mhi, mxhi);
            alo = fexp2(mlo - mnlo);
            ahi = fexp2(mhi - mnhi);

            float lslo = 0.f, lshi = 0.f;
#pragma unroll
            for (int nb = 0; nb < 8; nb++) {
                c[nb][0] = fexp2(c[nb][0] - mnlo);
                c[nb][1] = fexp2(c[nb][1] - mnlo);
                c[nb][2] = fexp2(c[nb][2] - mnhi);
                c[nb][3] = fexp2(c[nb][3] - mnhi);
                lslo += c[nb][0] + c[nb][1];
                lshi += c[nb][2] + c[nb][3];
            }
            lslo += __shfl_xor_sync(0xFFFFFFFFu, lslo, 1);
            lslo += __shfl_xor_sync(0xFFFFFFFFu, lslo, 2);
            lshi += __shfl_xor_sync(0xFFFFFFFFu, lshi, 1);
            lshi += __shfl_xor_sync(0xFFFFFFFFu, lshi, 2);

            bool noresc = __all_sync(0xFFFFFFFFu, (mnlo == mlo) & (mnhi == mhi));
            mlo = mnlo; mhi = mnhi;
            llo = llo * alo + lslo;
            lhi = lhi * ahi + lshi;

            if (!noresc) {
#pragma unroll
                for (int nb = 0; nb < 32; nb++) {
                    oacc[nb][0] *= alo; oacc[nb][1] *= alo;
                    oacc[nb][2] *= ahi; oacc[nb][3] *= ahi;
                }
            }

            // pack P into PV A-fragments (registers!)
#pragma unroll
            for (int kc2 = 0; kc2 < 4; kc2++) {
                prq[kc2].x = bf2pack(c[2*kc2][0],     c[2*kc2][1]);
                prq[kc2].y = bf2pack(c[2*kc2][2],     c[2*kc2][3]);
                prq[kc2].z = bf2pack(c[2*kc2+1][0],   c[2*kc2+1][1]);
                prq[kc2].w = bf2pack(c[2*kc2+1][2],   c[2*kc2+1][3]);
            }
        }

        // ---- O += P @ V : 16 rows x 256 cols ----
#pragma unroll
        for (int kc2 = 0; kc2 < 4; kc2++) {
#pragma unroll
            for (int nbp = 0; nbp < 32; nbp += 2) {
                uint4 bb = ldsm_x4t(&Vs[(kc2 * 16 + roffA) * VSTRH + nbp * 8 + coffA]);
                mma_bf16(oacc[nbp],     prq[kc2], bb.x, bb.y);
                mma_bf16(oacc[nbp + 1], prq[kc2], bb.z, bb.w);
            }
        }
    }

    // ---- epilogue: normalize, store ----
    float ilo = 1.f / llo, ihi = 1.f / lhi;
    float* Ob = O + ((size_t)b * NSEQ + qb * 128 + 16 * w) * CC;
#pragma unroll
    for (int nb = 0; nb < 32; nb++) {
        int col = 8 * nb + 2 * t;
        *(float2*)&Ob[(size_t)g       * CC + col] =
            make_float2(oacc[nb][0] * ilo, oacc[nb][1] * ilo);
        *(float2*)&Ob[(size_t)(g + 8) * CC + col] =
            make_float2(oacc[nb][2] * ihi, oacc[nb][3] * ihi);
    }
}

// ---------------------------------------------------------------------------
extern "C" void kernel_launch(void* const* d_in, const int* in_sizes, int n_in,
                              void* d_out, int out_size)
{
    const float* x  = (const float*)d_in[0];
    const float* wq = (const float*)d_in[1];
    const float* bq = (const float*)d_in[2];
    const float* wk = (const float*)d_in[3];
    const float* bk = (const float*)d_in[4];
    const float* wv = (const float*)d_in[5];
    const float* bv = (const float*)d_in[6];
    const float* wo = (const float*)d_in[7];
    const float* bo = (const float*)d_in[8];
    float* out = (float*)d_out;

    __nv_bfloat16 *qp, *kp, *vp;
    float* ap;
    cudaGetSymbolAddress((void**)&qp, g_q);
    cudaGetSymbolAddress((void**)&kp, g_k);
    cudaGetSymbolAddress((void**)&vp, g_v);
    cudaGetSymbolAddress((void**)&ap, g_att);

    const int M = BB * NSEQ;   // 16384
    const float SCLQ = 0.25506806f;   // log2(e)/sqrt(32)

    // Projections (tf32 tensor GEMM; q pre-scaled; q/k/v emitted as bf16)
    gemm_tf32_kernel<__nv_bfloat16><<<dim3(1, M / 128), 256>>>(x, wq, bq, nullptr, qp, M, DD, CC, SCLQ);
    gemm_tf32_kernel<__nv_bfloat16><<<dim3(1, M / 128), 256>>>(x, wk, bk, nullptr, kp, M, DD, CC, 1.f);
    gemm_tf32_kernel<__nv_bfloat16><<<dim3(CC / 64, M / 128), 256>>>(x, wv, bv, nullptr, vp, M, CC, CC, 1.f);

    // Fused-register flash attention
    cudaFuncSetAttribute(flash_fused_kernel, cudaFuncAttributeMaxDynamicSharedMemorySize,
                         FLASH_SMEM_BYTES);
    flash_fused_kernel<<<dim3(NSEQ / 128, BB), 256, FLASH_SMEM_BYTES>>>(qp, kp, vp, ap);

    // Output projection + bias + residual -> d_out (fp32)
    gemm_tf32_kernel<float><<<dim3(CC / 64, M / 128), 256>>>(ap, wo, bo, x, out, M, CC, CC, 1.f);
}

// round 7
// speedup vs baseline: 7.3111x; 1.1099x over previous
#include <cuda_runtime.h>
#include <cuda_bf16.h>
#include <math.h>
#include <stdint.h>

// Problem constants
#define BB 4
#define NSEQ 4096        // H*W
#define CC 256
#define DD 32

// Scratch (device globals)
__device__ __nv_bfloat16 g_q[BB * NSEQ * DD];
__device__ __nv_bfloat16 g_k[BB * NSEQ * DD];
__device__ __nv_bfloat16 g_v[BB * NSEQ * CC];
__device__ float         g_att[BB * NSEQ * CC];

// ---------------------------------------------------------------------------
// helpers
// ---------------------------------------------------------------------------
__device__ __forceinline__ uint32_t smaddr(const void* p) {
    return (uint32_t)__cvta_generic_to_shared(p);
}
__device__ __forceinline__ uint4 ldsm_x4(const void* p) {
    uint4 r; uint32_t a = smaddr(p);
    asm volatile("ldmatrix.sync.aligned.m8n8.x4.shared.b16 {%0,%1,%2,%3}, [%4];"
                 : "=r"(r.x), "=r"(r.y), "=r"(r.z), "=r"(r.w) : "r"(a));
    return r;
}
__device__ __forceinline__ uint4 ldsm_x4t(const void* p) {
    uint4 r; uint32_t a = smaddr(p);
    asm volatile("ldmatrix.sync.aligned.m8n8.x4.trans.shared.b16 {%0,%1,%2,%3}, [%4];"
                 : "=r"(r.x), "=r"(r.y), "=r"(r.z), "=r"(r.w) : "r"(a));
    return r;
}
__device__ __forceinline__ void mma_bf16(float* c, const uint4& a, uint32_t b0, uint32_t b1) {
    asm volatile(
        "mma.sync.aligned.m16n8k16.row.col.f32.bf16.bf16.f32 "
        "{%0,%1,%2,%3}, {%4,%5,%6,%7}, {%8,%9}, {%0,%1,%2,%3};"
        : "+f"(c[0]), "+f"(c[1]), "+f"(c[2]), "+f"(c[3])
        : "r"(a.x), "r"(a.y), "r"(a.z), "r"(a.w), "r"(b0), "r"(b1));
}
__device__ __forceinline__ void mma_tf32(float* c, const uint32_t* a, const uint32_t* b) {
    asm volatile(
        "mma.sync.aligned.m16n8k8.row.col.f32.tf32.tf32.f32 "
        "{%0,%1,%2,%3}, {%4,%5,%6,%7}, {%8,%9}, {%0,%1,%2,%3};"
        : "+f"(c[0]), "+f"(c[1]), "+f"(c[2]), "+f"(c[3])
        : "r"(a[0]), "r"(a[1]), "r"(a[2]), "r"(a[3]), "r"(b[0]), "r"(b[1]));
}
__device__ __forceinline__ float fexp2(float x) {
    float y; asm("ex2.approx.ftz.f32 %0, %1;" : "=f"(y) : "f"(x)); return y;
}
__device__ __forceinline__ uint32_t bf2pack(float lo, float hi) {
    uint32_t u; asm("cvt.rn.bf16x2.f32 %0, %1, %2;" : "=r"(u) : "f"(hi), "f"(lo)); return u;
}
__device__ __forceinline__ void cp16(uint32_t dst, const void* src) {
    asm volatile("cp.async.cg.shared.global [%0], [%1], 16;" :: "r"(dst), "l"(src));
}
__device__ __forceinline__ void cp16z(uint32_t dst, const void* src, int nbytes) {
    asm volatile("cp.async.cg.shared.global [%0], [%1], 16, %2;" :: "r"(dst), "l"(src), "r"(nbytes));
}
__device__ __forceinline__ void cp_commit() {
    asm volatile("cp.async.commit_group;");
}

// ---------------------------------------------------------------------------
// TF32 tensor GEMM, cp.async double-buffered. BM=128 BN=64 BK=32.
// A operand is raw fp32 (mma truncates to tf32). K % 32 == 0, M % 128 == 0.
// ---------------------------------------------------------------------------
#define GASTR 36
#define GWSTR 72
#define GEMM_SMEM_BYTES ((2 * 128 * GASTR + 2 * 32 * GWSTR) * 4)

template <typename OutT>
__global__ __launch_bounds__(256) void gemm_tf32_kernel(
    const float* __restrict__ A, const float* __restrict__ W,
    const float* __restrict__ bias, const float* __restrict__ res,
    OutT* __restrict__ Cm, int M, int N, int K, float outscale)
{
    extern __shared__ float gsm[];
    float* As0 = gsm;                       // 2 stages of 128*GASTR
    float* Ws0 = gsm + 2 * 128 * GASTR;     // 2 stages of 32*GWSTR

    const int tid  = threadIdx.x;
    const int lane = tid & 31;
    const int w    = tid >> 5;
    const int g    = lane >> 2;
    const int t    = lane & 3;
    const int wm   = w & 3;
    const int wn   = w >> 2;

    const int m0 = blockIdx.y * 128;
    const int n0 = blockIdx.x * 64;
    const int NK = K / 32;

    auto load_stage = [&](int kt) {
        int st = kt & 1;
        float* As = As0 + st * 128 * GASTR;
        float* Ws = Ws0 + st * 32 * GWSTR;
        int k0 = kt * 32;
#pragma unroll
        for (int i = 0; i < 4; i++) {
            int idx = tid + i * 256;
            int r = idx >> 3, c4 = idx & 7;
            cp16(smaddr(&As[r * GASTR + c4 * 4]),
                 &A[(size_t)(m0 + r) * K + k0 + c4 * 4]);
        }
#pragma unroll
        for (int i = 0; i < 2; i++) {
            int idx = tid + i * 256;
            int r = idx >> 4, c4 = idx & 15;
            int col = n0 + c4 * 4;
            const float* src = (col + 3 < N) ? &W[(size_t)(k0 + r) * N + col] : W;
            cp16z(smaddr(&Ws[r * GWSTR + c4 * 4]), src, (col + 3 < N) ? 16 : 0);
        }
        cp_commit();
    };

    float c[2][4][4];
#pragma unroll
    for (int mb = 0; mb < 2; mb++)
#pragma unroll
        for (int nb = 0; nb < 4; nb++)
#pragma unroll
            for (int j = 0; j < 4; j++) c[mb][nb][j] = 0.f;

    load_stage(0);
    if (NK > 1) load_stage(1);

    for (int kt = 0; kt < NK; kt++) {
        if (kt + 1 < NK) asm volatile("cp.async.wait_group 1;");
        else             asm volatile("cp.async.wait_group 0;");
        __syncthreads();

        const float* As = As0 + (kt & 1) * 128 * GASTR;
        const float* Ws = Ws0 + (kt & 1) * 32 * GWSTR;

#pragma unroll
        for (int kc = 0; kc < 4; kc++) {
            int kk = kc * 8;
            uint32_t a[2][4];
#pragma unroll
            for (int mb = 0; mb < 2; mb++) {
                int rbase = wm * 32 + mb * 16;
                a[mb][0] = __float_as_uint(As[(rbase + g)     * GASTR + kk + t]);
                a[mb][1] = __float_as_uint(As[(rbase + g + 8) * GASTR + kk + t]);
                a[mb][2] = __float_as_uint(As[(rbase + g)     * GASTR + kk + t + 4]);
                a[mb][3] = __float_as_uint(As[(rbase + g + 8) * GASTR + kk + t + 4]);
            }
#pragma unroll
            for (int nb = 0; nb < 4; nb++) {
                uint32_t b[2];
                int col = wn * 32 + nb * 8 + g;
                b[0] = __float_as_uint(Ws[(kk + t)     * GWSTR + col]);
                b[1] = __float_as_uint(Ws[(kk + t + 4) * GWSTR + col]);
                mma_tf32(c[0][nb], a[0], b);
                mma_tf32(c[1][nb], a[1], b);
            }
        }
        __syncthreads();
        if (kt + 2 < NK) load_stage(kt + 2);
    }

    // epilogue
#pragma unroll
    for (int mb = 0; mb < 2; mb++) {
        int rlo = m0 + wm * 32 + mb * 16 + g;
        int rhi = rlo + 8;
#pragma unroll
        for (int nb = 0; nb < 4; nb++) {
            int col = n0 + wn * 32 + nb * 8 + 2 * t;
            if (col < N) {
                float b0 = bias[col], b1 = bias[col + 1];
                float v00 = (c[mb][nb][0] + b0) * outscale, v01 = (c[mb][nb][1] + b1) * outscale;
                float v10 = (c[mb][nb][2] + b0) * outscale, v11 = (c[mb][nb][3] + b1) * outscale;
                if (res) {
                    v00 += res[(size_t)rlo * N + col]; v01 += res[(size_t)rlo * N + col + 1];
                    v10 += res[(size_t)rhi * N + col]; v11 += res[(size_t)rhi * N + col + 1];
                }
                if (sizeof(OutT) == 4) {
                    *(float2*)&((float*)Cm)[(size_t)rlo * N + col] = make_float2(v00, v01);
                    *(float2*)&((float*)Cm)[(size_t)rhi * N + col] = make_float2(v10, v11);
                } else {
                    ((uint32_t*)Cm)[((size_t)rlo * N + col) >> 1] = bf2pack(v00, v01);
                    ((uint32_t*)Cm)[((size_t)rhi * N + col) >> 1] = bf2pack(v10, v11);
                }
            }
        }
    }
}

// ---------------------------------------------------------------------------
// Fused-register bf16 flash attention, skewed software pipeline.
// 256 threads / 8 warps. BM=128 (warp owns 16 rows end-to-end), BN=64.
// Iteration kt: issue S-mma(kt) -> PV-mma(kt-1) (hides S latency) ->
// softmax(kt) -> rescale -> pack prq(kt). PV(NT-1) drained after loop.
// 4-STAGE K/V ring (slot = kt & 3): with the skew, V(kt-1) is read in
// iteration kt while tile kt+2 streams in, so 4 slots must be live.
// ---------------------------------------------------------------------------
#define KSTRH 40
#define VSTRH 264
#define KSTAGE (64 * KSTRH)
#define VSTAGE (64 * VSTRH)
#define NSTAGES 4
#define FLASH_SMEM_BYTES ((NSTAGES * KSTAGE + NSTAGES * VSTAGE) * 2)   // 152 KB

__device__ __forceinline__ void flash_load_tile(
    const __nv_bfloat16* __restrict__ Kb, const __nv_bfloat16* __restrict__ Vb,
    __nv_bfloat16* Ksb, __nv_bfloat16* Vsb, int kt, int tid, int kr, int kc16)
{
    int s = kt & 3;
    __nv_bfloat16* Kn = Ksb + s * KSTAGE;
    __nv_bfloat16* Vn = Vsb + s * VSTAGE;
    const __nv_bfloat16* Kgp = Kb + (size_t)kt * 64 * DD;
    const __nv_bfloat16* Vgp = Vb + (size_t)kt * 64 * CC;
    cp16(smaddr(&Kn[kr * KSTRH + kc16 * 8]), &Kgp[(size_t)kr * DD + kc16 * 8]);
#pragma unroll
    for (int i = 0; i < 8; i++) {
        int l = tid + i * 256;
        int r = l >> 5, cc = l & 31;
        cp16(smaddr(&Vn[r * VSTRH + cc * 8]), &Vgp[(size_t)r * CC + cc * 8]);
    }
    cp_commit();
}

__global__ __launch_bounds__(256) void flash_fused_kernel(
    const __nv_bfloat16* __restrict__ Q, const __nv_bfloat16* __restrict__ Kg,
    const __nv_bfloat16* __restrict__ V, float* __restrict__ O)
{
    extern __shared__ __nv_bfloat16 sm[];
    __nv_bfloat16* Ksb = sm;
    __nv_bfloat16* Vsb = sm + NSTAGES * KSTAGE;

    const int tid  = threadIdx.x;
    const int lane = tid & 31;
    const int w    = tid >> 5;
    const int g    = lane >> 2;
    const int t    = lane & 3;

    const int qb = blockIdx.x;
    const int b  = blockIdx.y;

    const __nv_bfloat16* Qb = Q  + ((size_t)b * NSEQ + qb * 128 + 16 * w) * DD;
    const __nv_bfloat16* Kb = Kg + (size_t)b * NSEQ * DD;
    const __nv_bfloat16* Vb = V  + (size_t)b * NSEQ * CC;

    const int roffA = (lane & 7) + ((lane >> 3) & 1) * 8;
    const int coffA = ((lane >> 4) & 1) * 8;
    const int roffB = (lane & 7) + ((lane >> 4) & 1) * 8;
    const int coffB = ((lane >> 3) & 1) * 8;

    const int kr = tid >> 2, kc16 = tid & 3;
    const int NT = NSEQ / 64;   // 64 tiles

    flash_load_tile(Kb, Vb, Ksb, Vsb, 0, tid, kr, kc16);
    flash_load_tile(Kb, Vb, Ksb, Vsb, 1, tid, kr, kc16);

    // Q A-fragments straight from gmem
    uint4 qa[2];
#pragma unroll
    for (int kc = 0; kc < 2; kc++) {
        qa[kc].x = *(const uint32_t*)&Qb[(size_t)g       * DD + kc * 16 + 2 * t];
        qa[kc].y = *(const uint32_t*)&Qb[(size_t)(g + 8) * DD + kc * 16 + 2 * t];
        qa[kc].z = *(const uint32_t*)&Qb[(size_t)g       * DD + kc * 16 + 8 + 2 * t];
        qa[kc].w = *(const uint32_t*)&Qb[(size_t)(g + 8) * DD + kc * 16 + 8 + 2 * t];
    }

    float mlo = -INFINITY, mhi = -INFINITY, llo = 0.f, lhi = 0.f;
    uint4 prq[4];   // P fragments of the PREVIOUS tile

    float oacc[32][4];
#pragma unroll
    for (int nb = 0; nb < 32; nb++)
#pragma unroll
        for (int j = 0; j < 4; j++) oacc[nb][j] = 0.f;

    for (int kt = 0; kt < NT; kt++) {
        __syncthreads();   // all warps done with iter kt-1 (slot (kt+2)&3 = (kt-2)&3 free)

        if (kt + 2 < NT) {
            flash_load_tile(Kb, Vb, Ksb, Vsb, kt + 2, tid, kr, kc16);
            asm volatile("cp.async.wait_group 2;");
        } else if (kt + 1 < NT) {
            asm volatile("cp.async.wait_group 1;");
        } else {
            asm volatile("cp.async.wait_group 0;");
        }
        __syncthreads();   // tile kt visible to all

        const __nv_bfloat16* Ks = Ksb + (kt & 3) * KSTAGE;

        // ---- issue S-mma(kt) ----
        float sc[8][4];
#pragma unroll
        for (int nb = 0; nb < 8; nb++)
#pragma unroll
            for (int j = 0; j < 4; j++) sc[nb][j] = 0.f;

#pragma unroll
        for (int kc = 0; kc < 2; kc++) {
#pragma unroll
            for (int nbp = 0; nbp < 8; nbp += 2) {
                uint4 bb = ldsm_x4(&Ks[(nbp * 8 + roffB) * KSTRH + kc * 16 + coffB]);
                mma_bf16(sc[nbp],     qa[kc], bb.x, bb.y);
                mma_bf16(sc[nbp + 1], qa[kc], bb.z, bb.w);
            }
        }

        // ---- PV-mma(kt-1): independent of S(kt), hides its latency ----
        if (kt > 0) {
            const __nv_bfloat16* Vp = Vsb + ((kt - 1) & 3) * VSTAGE;
#pragma unroll
            for (int kc2 = 0; kc2 < 4; kc2++) {
#pragma unroll
                for (int nbp = 0; nbp < 32; nbp += 2) {
                    uint4 bb = ldsm_x4t(&Vp[(kc2 * 16 + roffA) * VSTRH + nbp * 8 + coffA]);
                    mma_bf16(oacc[nbp],     prq[kc2], bb.x, bb.y);
                    mma_bf16(oacc[nbp + 1], prq[kc2], bb.z, bb.w);
                }
            }
        }

        // ---- softmax(kt): S results have landed by now ----
        float mxlo = -INFINITY, mxhi = -INFINITY;
#pragma unroll
        for (int nb = 0; nb < 8; nb++) {
            mxlo = fmaxf(mxlo, fmaxf(sc[nb][0], sc[nb][1]));
            mxhi = fmaxf(mxhi, fmaxf(sc[nb][2], sc[nb][3]));
        }
        mxlo = fmaxf(mxlo, __shfl_xor_sync(0xFFFFFFFFu, mxlo, 1));
        mxlo = fmaxf(mxlo, __shfl_xor_sync(0xFFFFFFFFu, mxlo, 2));
        mxhi = fmaxf(mxhi, __shfl_xor_sync(0xFFFFFFFFu, mxhi, 1));
        mxhi = fmaxf(mxhi, __shfl_xor_sync(0xFFFFFFFFu, mxhi, 2));

        float mnlo = fmaxf(mlo, mxlo), mnhi = fmaxf(mhi, mxhi);
        float alo = fexp2(mlo - mnlo), ahi = fexp2(mhi - mnhi);

        float lslo = 0.f, lshi = 0.f;
#pragma unroll
        for (int nb = 0; nb < 8; nb++) {
            sc[nb][0] = fexp2(sc[nb][0] - mnlo);
            sc[nb][1] = fexp2(sc[nb][1] - mnlo);
            sc[nb][2] = fexp2(sc[nb][2] - mnhi);
            sc[nb][3] = fexp2(sc[nb][3] - mnhi);
            lslo += sc[nb][0] + sc[nb][1];
            lshi += sc[nb][2] + sc[nb][3];
        }
        lslo += __shfl_xor_sync(0xFFFFFFFFu, lslo, 1);
        lslo += __shfl_xor_sync(0xFFFFFFFFu, lslo, 2);
        lshi += __shfl_xor_sync(0xFFFFFFFFu, lshi, 1);
        lshi += __shfl_xor_sync(0xFFFFFFFFu, lshi, 2);

        bool noresc = __all_sync(0xFFFFFFFFu, (mnlo == mlo) & (mnhi == mhi));
        mlo = mnlo; mhi = mnhi;
        llo = llo * alo + lslo;
        lhi = lhi * ahi + lshi;

        if (!noresc) {
#pragma unroll
            for (int nb = 0; nb < 32; nb++) {
                oacc[nb][0] *= alo; oacc[nb][1] *= alo;
                oacc[nb][2] *= ahi; oacc[nb][3] *= ahi;
            }
        }

        // pack P(kt) into PV A-fragments
#pragma unroll
        for (int kc2 = 0; kc2 < 4; kc2++) {
            prq[kc2].x = bf2pack(sc[2*kc2][0],   sc[2*kc2][1]);
            prq[kc2].y = bf2pack(sc[2*kc2][2],   sc[2*kc2][3]);
            prq[kc2].z = bf2pack(sc[2*kc2+1][0], sc[2*kc2+1][1]);
            prq[kc2].w = bf2pack(sc[2*kc2+1][2], sc[2*kc2+1][3]);
        }
    }

    // ---- drain PV(NT-1) ----
    {
        const __nv_bfloat16* Vp = Vsb + ((NT - 1) & 3) * VSTAGE;
#pragma unroll
        for (int kc2 = 0; kc2 < 4; kc2++) {
#pragma unroll
            for (int nbp = 0; nbp < 32; nbp += 2) {
                uint4 bb = ldsm_x4t(&Vp[(kc2 * 16 + roffA) * VSTRH + nbp * 8 + coffA]);
                mma_bf16(oacc[nbp],     prq[kc2], bb.x, bb.y);
                mma_bf16(oacc[nbp + 1], prq[kc2], bb.z, bb.w);
            }
        }
    }

    // ---- epilogue: normalize, store ----
    float ilo = 1.f / llo, ihi = 1.f / lhi;
    float* Ob = O + ((size_t)b * NSEQ + qb * 128 + 16 * w) * CC;
#pragma unroll
    for (int nb = 0; nb < 32; nb++) {
        int col = 8 * nb + 2 * t;
        *(float2*)&Ob[(size_t)g       * CC + col] =
            make_float2(oacc[nb][0] * ilo, oacc[nb][1] * ilo);
        *(float2*)&Ob[(size_t)(g + 8) * CC + col] =
            make_float2(oacc[nb][2] * ihi, oacc[nb][3] * ihi);
    }
}

// ---------------------------------------------------------------------------
extern "C" void kernel_launch(void* const* d_in, const int* in_sizes, int n_in,
                              void* d_out, int out_size)
{
    const float* x  = (const float*)d_in[0];
    const float* wq = (const float*)d_in[1];
    const float* bq = (const float*)d_in[2];
    const float* wk = (const float*)d_in[3];
    const float* bk = (const float*)d_in[4];
    const float* wv = (const float*)d_in[5];
    const float* bv = (const float*)d_in[6];
    const float* wo = (const float*)d_in[7];
    const float* bo = (const float*)d_in[8];
    float* out = (float*)d_out;

    __nv_bfloat16 *qp, *kp, *vp;
    float* ap;
    cudaGetSymbolAddress((void**)&qp, g_q);
    cudaGetSymbolAddress((void**)&kp, g_k);
    cudaGetSymbolAddress((void**)&vp, g_v);
    cudaGetSymbolAddress((void**)&ap, g_att);

    const int M = BB * NSEQ;   // 16384
    const float SCLQ = 0.25506806f;   // log2(e)/sqrt(32)

    cudaFuncSetAttribute(gemm_tf32_kernel<__nv_bfloat16>,
                         cudaFuncAttributeMaxDynamicSharedMemorySize, GEMM_SMEM_BYTES);
    cudaFuncSetAttribute(gemm_tf32_kernel<float>,
                         cudaFuncAttributeMaxDynamicSharedMemorySize, GEMM_SMEM_BYTES);
    cudaFuncSetAttribute(flash_fused_kernel,
                         cudaFuncAttributeMaxDynamicSharedMemorySize, FLASH_SMEM_BYTES);

    // Projections (q pre-scaled by log2(e)/sqrt(D); q/k/v emitted as bf16)
    gemm_tf32_kernel<__nv_bfloat16><<<dim3(1, M / 128), 256, GEMM_SMEM_BYTES>>>(
        x, wq, bq, nullptr, qp, M, DD, CC, SCLQ);
    gemm_tf32_kernel<__nv_bfloat16><<<dim3(1, M / 128), 256, GEMM_SMEM_BYTES>>>(
        x, wk, bk, nullptr, kp, M, DD, CC, 1.f);
    gemm_tf32_kernel<__nv_bfloat16><<<dim3(CC / 64, M / 128), 256, GEMM_SMEM_BYTES>>>(
        x, wv, bv, nullptr, vp, M, CC, CC, 1.f);

    // Flash attention (skewed pipeline, 4-stage ring)
    flash_fused_kernel<<<dim3(NSEQ / 128, BB), 256, FLASH_SMEM_BYTES>>>(qp, kp, vp, ap);

    // Output projection + bias + residual -> d_out (fp32)
    gemm_tf32_kernel<float><<<dim3(CC / 64, M / 128), 256, GEMM_SMEM_BYTES>>>(
        ap, wo, bo, x, out, M, CC, CC, 1.f);
}